// round 7
// baseline (speedup 1.0000x reference)
#include <cuda_runtime.h>
#include <math.h>

#define NN    50000
#define EE    800000
#define TT    32
#define CH    64          // CHUNK = CIN/T
#define HH    96
#define CIN   2048
#define EPS_BN 1e-5f
#define VTH    0.005f
#define NB    782         // blocks per role: ceil(NN/64)

// ---------------- persistent device scratch (no allocation allowed) -------
__device__ int   g_deg[NN];
__device__ int   g_cnt[NN];
__device__ int   g_off[NN + 1];
__device__ int2  g_epack[EE];           // {src, weight bits}
__device__ float g_dinv[NN];
__device__ float g_snorm[NN];
__device__ float g_rsum[NN];
__device__ float g_h2[2][NN * HH];      // double-buffered bns(elu(z1))
__device__ float g_v[NN * HH];          // PLIF membrane state
__device__ float g_ss[HH];              // shared-BN scale
__device__ float g_cs[HH];              // shared-BN shift
__device__ float g_lwsum[HH];           // sum(lin_w, axis=0)
__device__ float g_s1[TT * CH];         // input-BN scale, all steps
__device__ float g_c1[TT * CH];         // input-BN shift, all steps

// ---------------- preprocessing (exactly 5 launches) ----------------------
// #1: zero deg/cnt/v + all affine params + lwsum
__global__ void k_pre0(const float* __restrict__ bg, const float* __restrict__ bb,
                       const float* __restrict__ bm, const float* __restrict__ bv,
                       const float* __restrict__ lw,
                       const float* __restrict__ g1, const float* __restrict__ b1,
                       const float* __restrict__ m1, const float* __restrict__ v1) {
    int i = blockIdx.x * blockDim.x + threadIdx.x;
    if (i < NN * HH) g_v[i] = 0.f;
    if (i < NN) { g_deg[i] = 0; g_cnt[i] = 0; }
    if (i < TT * CH) {
        float s = g1[i] * rsqrtf(v1[i] + EPS_BN);
        g_s1[i] = s;
        g_c1[i] = b1[i] - m1[i] * s;
    }
    if (i < HH) {
        float s = bg[i] * rsqrtf(bv[i] + EPS_BN);
        g_ss[i] = s;
        g_cs[i] = bb[i] - bm[i] * s;
        float acc = 0.f;
        for (int o = 0; o < HH; o++) acc += lw[o * HH + i];
        g_lwsum[i] = acc;
    }
}

// #2: degree histogram
__global__ void k_deg(const int* __restrict__ ei) {
    int e = blockIdx.x * blockDim.x + threadIdx.x;
    if (e < EE) atomicAdd(&g_deg[ei[EE + e]], 1);
}

// #3: dinv/snorm + single-block exclusive scan of deg -> off
__global__ void k_scan_dinv() {
    __shared__ int buf[1024];
    __shared__ int carry;
    int tid = threadIdx.x;
    if (tid == 0) carry = 0;
    __syncthreads();
    for (int base = 0; base < NN; base += 1024) {
        int i = base + tid;
        int val = 0;
        if (i < NN) {
            val = g_deg[i];
            float d = (float)(val + 1);
            g_dinv[i]  = rsqrtf(d);
            g_snorm[i] = 1.0f / d;
        }
        buf[tid] = val;
        __syncthreads();
        for (int off = 1; off < 1024; off <<= 1) {
            int t2 = (tid >= off) ? buf[tid - off] : 0;
            __syncthreads();
            buf[tid] += t2;
            __syncthreads();
        }
        if (i < NN) g_off[i] = carry + buf[tid] - val;   // exclusive
        __syncthreads();
        if (tid == 0) carry += buf[1023];
        __syncthreads();
    }
    if (tid == 0) g_off[NN] = carry;
}

// #4: CSR placement with packed (src, weight)
__global__ void k_fill(const int* __restrict__ ei) {
    int e = blockIdx.x * blockDim.x + threadIdx.x;
    if (e < EE) {
        int s = ei[e];
        int d = ei[EE + e];
        int pos = g_off[d] + atomicAdd(&g_cnt[d], 1);
        g_epack[pos] = make_int2(s, __float_as_int(g_dinv[s] * g_dinv[d]));
    }
}

// #5: row sums of full normalized adjacency
__global__ void k_rsum() {
    int n = blockIdx.x * blockDim.x + threadIdx.x;
    if (n < NN) {
        float r = g_snorm[n];
        int e1 = g_off[n + 1];
        for (int e = g_off[n]; e < e1; e++) r += __int_as_float(g_epack[e].y);
        g_rsum[n] = r;
    }
}

// ---------------- heterogeneous step kernel -------------------------------
// role step1: agg(x chunk)+BN fold -> GEMM1(64->96) -> elu -> bns -> h2[buf]
// role step2: agg(h2[buf]) -> GEMM2(96->96) -> PLIF -> spike -> decode
// dynamic smem (step2 layout is the max): a_s[96*68] | w_s[96*96] | lws[96] | nacc[64]
#define SMEM_FLOATS (HH * 68 + HH * HH + HH + 64)

__device__ __forceinline__ void step1_body(
    float* dsm, int bid, int t,
    const float* __restrict__ x, const float* __restrict__ w1,
    const float* __restrict__ b1)
{
    float* a_s = dsm;                 // [64][68]
    float* w_s = dsm + CH * 68;       // [64][96]

    int tid  = threadIdx.x;
    int warp = tid >> 5;
    int lane = tid & 31;
    int m0   = bid * 64;

    const float* wt = w1 + t * CH * HH;
    for (int idx = tid; idx < CH * HH; idx += 384)
        w_s[idx] = wt[idx];

    const float* s1 = g_s1 + t * CH;
    const float* c1 = g_c1 + t * CH;
    float s1a = s1[lane], s1b = s1[lane + 32];
    float c1a = c1[lane], c1b = c1[lane + 32];
    for (int m = warp; m < 64; m += 12) {
        int n = m0 + m;
        if (n >= NN) { a_s[lane * 68 + m] = 0.f; a_s[(lane + 32) * 68 + m] = 0.f; continue; }
        const float* xb = x + (size_t)n * CIN + t * CH;
        float sn = g_snorm[n];
        float a0 = sn * xb[lane];
        float a1 = sn * xb[lane + 32];
        int e0 = g_off[n], e1 = g_off[n + 1];
#pragma unroll 2
        for (int e = e0; e < e1; e++) {
            int2  p = g_epack[e];
            float w = __int_as_float(p.y);
            const float* xs = x + (size_t)p.x * CIN + t * CH;
            a0 += w * xs[lane];
            a1 += w * xs[lane + 32];
        }
        float r = g_rsum[n];
        a_s[lane * 68 + m]        = a0 * s1a + r * c1a;
        a_s[(lane + 32) * 68 + m] = a1 * s1b + r * c1b;
    }
    __syncthreads();

    int mt = (tid & 15) * 4;   // 0..60
    int jt = (tid >> 4) * 4;   // 0..92
    float acc[4][4] = {};
#pragma unroll 8
    for (int k = 0; k < CH; k++) {
        float4 av = *(const float4*)&a_s[k * 68 + mt];
        float4 wv = *(const float4*)&w_s[k * HH + jt];
        acc[0][0] += av.x * wv.x; acc[0][1] += av.x * wv.y; acc[0][2] += av.x * wv.z; acc[0][3] += av.x * wv.w;
        acc[1][0] += av.y * wv.x; acc[1][1] += av.y * wv.y; acc[1][2] += av.y * wv.z; acc[1][3] += av.y * wv.w;
        acc[2][0] += av.z * wv.x; acc[2][1] += av.z * wv.y; acc[2][2] += av.z * wv.z; acc[2][3] += av.z * wv.w;
        acc[3][0] += av.w * wv.x; acc[3][1] += av.w * wv.y; acc[3][2] += av.w * wv.z; acc[3][3] += av.w * wv.w;
    }

    const float* b1t = b1 + t * HH;
    float bj[4], ssj[4], csj[4];
#pragma unroll
    for (int j = 0; j < 4; j++) {
        bj[j]  = b1t[jt + j];
        ssj[j] = g_ss[jt + j];
        csj[j] = g_cs[jt + j];
    }
    float* h2 = g_h2[t & 1];
#pragma unroll
    for (int i = 0; i < 4; i++) {
        int n = m0 + mt + i;
        if (n < NN) {
            float o[4];
#pragma unroll
            for (int j = 0; j < 4; j++) {
                float z = acc[i][j] + bj[j];
                z = (z > 0.f) ? z : expm1f(z);
                o[j] = z * ssj[j] + csj[j];
            }
            *(float4*)&h2[n * HH + jt] = make_float4(o[0], o[1], o[2], o[3]);
        }
    }
}

__device__ __forceinline__ void step2_body(
    float* dsm, int bid, int t,
    const float* __restrict__ w2, const float* __restrict__ b2,
    const float* __restrict__ tau, float* __restrict__ out)
{
    float* a_s  = dsm;                    // [96][68]
    float* w_s  = dsm + HH * 68;          // [96][96]
    float* lws  = w_s + HH * HH;          // [96]
    float* nacc = lws + HH;               // [64]

    int tid  = threadIdx.x;
    int warp = tid >> 5;
    int lane = tid & 31;
    int m0   = bid * 64;

    if (tid < HH) lws[tid] = g_lwsum[tid];
    if (tid < 64) nacc[tid] = 0.f;
    for (int idx = tid; idx < HH * HH; idx += 384)
        w_s[idx] = w2[idx];

    const float* h2 = g_h2[t & 1];
    for (int m = warp; m < 64; m += 12) {
        int n = m0 + m;
        if (n >= NN) {
            a_s[lane * 68 + m] = 0.f;
            a_s[(lane + 32) * 68 + m] = 0.f;
            a_s[(lane + 64) * 68 + m] = 0.f;
            continue;
        }
        const float* hb = h2 + n * HH;
        float sn = g_snorm[n];
        float a0 = sn * hb[lane];
        float a1 = sn * hb[lane + 32];
        float a2 = sn * hb[lane + 64];
        int e0 = g_off[n], e1 = g_off[n + 1];
#pragma unroll 2
        for (int e = e0; e < e1; e++) {
            int2  p = g_epack[e];
            float w = __int_as_float(p.y);
            const float* hs = h2 + p.x * HH;
            a0 += w * hs[lane];
            a1 += w * hs[lane + 32];
            a2 += w * hs[lane + 64];
        }
        a_s[lane * 68 + m]        = a0;
        a_s[(lane + 32) * 68 + m] = a1;
        a_s[(lane + 64) * 68 + m] = a2;
    }
    __syncthreads();

    int mt = (tid & 15) * 4;
    int jt = (tid >> 4) * 4;
    float acc[4][4] = {};
#pragma unroll 8
    for (int k = 0; k < HH; k++) {
        float4 av = *(const float4*)&a_s[k * 68 + mt];
        float4 wv = *(const float4*)&w_s[k * HH + jt];
        acc[0][0] += av.x * wv.x; acc[0][1] += av.x * wv.y; acc[0][2] += av.x * wv.z; acc[0][3] += av.x * wv.w;
        acc[1][0] += av.y * wv.x; acc[1][1] += av.y * wv.y; acc[1][2] += av.y * wv.z; acc[1][3] += av.y * wv.w;
        acc[2][0] += av.z * wv.x; acc[2][1] += av.z * wv.y; acc[2][2] += av.z * wv.z; acc[2][3] += av.z * wv.w;
        acc[3][0] += av.w * wv.x; acc[3][1] += av.w * wv.y; acc[3][2] += av.w * wv.z; acc[3][3] += av.w * wv.w;
    }

    float tauv = *tau;
    float bj[4], lj[4];
#pragma unroll
    for (int j = 0; j < 4; j++) { bj[j] = b2[jt + j]; lj[j] = lws[jt + j]; }

#pragma unroll
    for (int i = 0; i < 4; i++) {
        int n = m0 + mt + i;
        if (n < NN) {
            float4 vv = *(float4*)&g_v[n * HH + jt];
            float vc[4] = {vv.x, vv.y, vv.z, vv.w};
            float vo[4];
            float pl = 0.f;
#pragma unroll
            for (int j = 0; j < 4; j++) {
                float dv = acc[i][j] + bj[j];
                float q  = dv - vc[j];
                float vnew = vc[j] + ((tauv == 1.0f) ? q : q / tauv);
                float u = vnew - VTH;
                bool sp = (u > 0.f);
                vo[j] = sp ? 0.f : vnew;
                if (sp) pl += lj[j];
            }
            *(float4*)&g_v[n * HH + jt] = make_float4(vo[0], vo[1], vo[2], vo[3]);
            atomicAdd(&nacc[mt + i], pl);
        }
    }
    __syncthreads();
    if (tid < 64) {
        int n = m0 + tid;
        if (n < NN) out[t * NN + n] = nacc[tid];
    }
}

// heterogeneous launch: if t2>=0, blocks [0,NB) run step2(t2);
// if t1>=0, the remaining NB blocks run step1(t1).
__global__ __launch_bounds__(384) void k_step(
    const float* __restrict__ x, const float* __restrict__ w1,
    const float* __restrict__ b1, const float* __restrict__ w2,
    const float* __restrict__ b2, const float* __restrict__ tau,
    float* __restrict__ out, int t1, int t2)
{
    extern __shared__ float dsm[];
    if (t2 >= 0 && blockIdx.x < NB) {
        step2_body(dsm, blockIdx.x, t2, w2, b2, tau, out);
    } else {
        int bid = (t2 >= 0) ? (blockIdx.x - NB) : blockIdx.x;
        step1_body(dsm, bid, t1, x, w1, b1);
    }
}

// ---------------- launch --------------------------------------------------
extern "C" void kernel_launch(void* const* d_in, const int* in_sizes, int n_in,
                              void* d_out, int out_size) {
    const float* x      = (const float*)d_in[0];
    const int*   ei     = (const int*)  d_in[1];
    const float* w1     = (const float*)d_in[2];
    const float* b1     = (const float*)d_in[3];
    const float* bn1_g  = (const float*)d_in[4];
    const float* bn1_b  = (const float*)d_in[5];
    const float* bn1_m  = (const float*)d_in[6];
    const float* bn1_v  = (const float*)d_in[7];
    const float* bns_g  = (const float*)d_in[8];
    const float* bns_b  = (const float*)d_in[9];
    const float* bns_m  = (const float*)d_in[10];
    const float* bns_v  = (const float*)d_in[11];
    const float* w2     = (const float*)d_in[12];
    const float* b2     = (const float*)d_in[13];
    const float* lin_w  = (const float*)d_in[14];
    const float* tau    = (const float*)d_in[15];
    float* out = (float*)d_out;

    static bool attr_set = false;
    if (!attr_set) {
        cudaFuncSetAttribute(k_step, cudaFuncAttributeMaxDynamicSharedMemorySize,
                             SMEM_FLOATS * (int)sizeof(float));
        attr_set = true;
    }

    int smem = SMEM_FLOATS * (int)sizeof(float);

    // exactly 5 preprocessing launches (so ncu -s 5 captures the hot loop)
    k_pre0<<<(NN * HH + 255) / 256, 256>>>(bns_g, bns_b, bns_m, bns_v, lin_w,
                                           bn1_g, bn1_b, bn1_m, bn1_v);
    k_deg<<<(EE + 255) / 256, 256>>>(ei);
    k_scan_dinv<<<1, 1024>>>();
    k_fill<<<(EE + 255) / 256, 256>>>(ei);
    k_rsum<<<(NN + 255) / 256, 256>>>();

    // software-pipelined hot loop: launch L runs step2(L-1) || step1(L)
    k_step<<<NB, 384, smem>>>(x, w1, b1, w2, b2, tau, out, 0, -1);
    for (int t = 1; t < TT; t++)
        k_step<<<2 * NB, 384, smem>>>(x, w1, b1, w2, b2, tau, out, t, t - 1);
    k_step<<<NB, 384, smem>>>(x, w1, b1, w2, b2, tau, out, -1, TT - 1);
}

// round 8
// speedup vs baseline: 1.0476x; 1.0476x over previous
#include <cuda_runtime.h>
#include <math.h>

#define NN    50000
#define EE    800000
#define TT    32
#define CH    64          // CHUNK = CIN/T
#define HH    96
#define CIN   2048
#define EPS_BN 1e-5f
#define VTH    0.005f

// ---------------- persistent device scratch (no allocation allowed) -------
__device__ int   g_deg[NN];
__device__ int   g_cnt[NN];
__device__ int   g_off[NN + 1];
__device__ int2  g_epack[EE];           // {src, weight bits}
__device__ float g_dinv[NN];
__device__ float g_snorm[NN];
__device__ float g_rsum[NN];
__device__ float g_h2[NN * HH];         // bns(elu(z1))
__device__ float g_v[NN * HH];          // PLIF membrane state
__device__ float g_ss[HH];              // shared-BN scale
__device__ float g_cs[HH];              // shared-BN shift
__device__ float g_lwsum[HH];           // sum(lin_w, axis=0)
__device__ float g_s1[TT * CH];         // input-BN scale, all steps
__device__ float g_c1[TT * CH];         // input-BN shift, all steps

// ---------------- preprocessing (exactly 5 launches) ----------------------
__global__ void k_pre0(const float* __restrict__ bg, const float* __restrict__ bb,
                       const float* __restrict__ bm, const float* __restrict__ bv,
                       const float* __restrict__ lw,
                       const float* __restrict__ g1, const float* __restrict__ b1,
                       const float* __restrict__ m1, const float* __restrict__ v1) {
    int i = blockIdx.x * blockDim.x + threadIdx.x;
    if (i < NN * HH) g_v[i] = 0.f;
    if (i < NN) { g_deg[i] = 0; g_cnt[i] = 0; }
    if (i < TT * CH) {
        float s = g1[i] * rsqrtf(v1[i] + EPS_BN);
        g_s1[i] = s;
        g_c1[i] = b1[i] - m1[i] * s;
    }
    if (i < HH) {
        float s = bg[i] * rsqrtf(bv[i] + EPS_BN);
        g_ss[i] = s;
        g_cs[i] = bb[i] - bm[i] * s;
        float acc = 0.f;
        for (int o = 0; o < HH; o++) acc += lw[o * HH + i];
        g_lwsum[i] = acc;
    }
}

__global__ void k_deg(const int* __restrict__ ei) {
    int e = blockIdx.x * blockDim.x + threadIdx.x;
    if (e < EE) atomicAdd(&g_deg[ei[EE + e]], 1);
}

__global__ void k_scan_dinv() {
    __shared__ int buf[1024];
    __shared__ int carry;
    int tid = threadIdx.x;
    if (tid == 0) carry = 0;
    __syncthreads();
    for (int base = 0; base < NN; base += 1024) {
        int i = base + tid;
        int val = 0;
        if (i < NN) {
            val = g_deg[i];
            float d = (float)(val + 1);
            g_dinv[i]  = rsqrtf(d);
            g_snorm[i] = 1.0f / d;
        }
        buf[tid] = val;
        __syncthreads();
        for (int off = 1; off < 1024; off <<= 1) {
            int t2 = (tid >= off) ? buf[tid - off] : 0;
            __syncthreads();
            buf[tid] += t2;
            __syncthreads();
        }
        if (i < NN) g_off[i] = carry + buf[tid] - val;   // exclusive
        __syncthreads();
        if (tid == 0) carry += buf[1023];
        __syncthreads();
    }
    if (tid == 0) g_off[NN] = carry;
}

__global__ void k_fill(const int* __restrict__ ei) {
    int e = blockIdx.x * blockDim.x + threadIdx.x;
    if (e < EE) {
        int s = ei[e];
        int d = ei[EE + e];
        int pos = g_off[d] + atomicAdd(&g_cnt[d], 1);
        g_epack[pos] = make_int2(s, __float_as_int(g_dinv[s] * g_dinv[d]));
    }
}

__global__ void k_rsum() {
    int n = blockIdx.x * blockDim.x + threadIdx.x;
    if (n < NN) {
        float r = g_snorm[n];
        int e1 = g_off[n + 1];
        for (int e = g_off[n]; e < e1; e++) r += __int_as_float(g_epack[e].y);
        g_rsum[n] = r;
    }
}

// ---------------- step kernel 1: agg(x chunk)+BN fold -> GEMM1 -> elu -> bns
// 64-node tile, 384 threads. static smem ~42KB.
__global__ __launch_bounds__(384, 3) void k_step1(
    const float* __restrict__ x, const float* __restrict__ w1,
    const float* __restrict__ b1, int t)
{
    __shared__ float a_s[CH][68];     // [k][m]
    __shared__ float w_s[CH][HH];

    int tid  = threadIdx.x;
    int warp = tid >> 5;
    int lane = tid & 31;
    int m0   = blockIdx.x * 64;

    const float* wt = w1 + t * CH * HH;
    for (int idx = tid; idx < CH * HH; idx += 384)
        w_s[idx / HH][idx % HH] = wt[idx];

    // fused aggregation: lane handles channels 2*lane, 2*lane+1 (float2)
    const float* s1 = g_s1 + t * CH;
    const float* c1 = g_c1 + t * CH;
    float s1a = s1[2 * lane], s1b = s1[2 * lane + 1];
    float c1a = c1[2 * lane], c1b = c1[2 * lane + 1];
    for (int m = warp; m < 64; m += 12) {
        int n = m0 + m;
        if (n >= NN) { a_s[2 * lane][m] = 0.f; a_s[2 * lane + 1][m] = 0.f; continue; }
        const float2* xb = (const float2*)(x + (size_t)n * CIN + t * CH);
        float sn = g_snorm[n];
        float2 xv = __ldcg(xb + lane);
        float a0 = sn * xv.x;
        float a1 = sn * xv.y;
        int e0 = g_off[n], e1 = g_off[n + 1];
#pragma unroll 4
        for (int e = e0; e < e1; e++) {
            int2  p = __ldcg(&g_epack[e]);
            float w = __int_as_float(p.y);
            float2 v = __ldcg((const float2*)(x + (size_t)p.x * CIN + t * CH) + lane);
            a0 += w * v.x;
            a1 += w * v.y;
        }
        float r = g_rsum[n];
        a_s[2 * lane][m]     = a0 * s1a + r * c1a;
        a_s[2 * lane + 1][m] = a1 * s1b + r * c1b;
    }
    __syncthreads();

    int mt = (tid & 15) * 4;   // 0..60
    int jt = (tid >> 4) * 4;   // 0..92
    float acc[4][4] = {};
#pragma unroll 8
    for (int k = 0; k < CH; k++) {
        float4 av = *(const float4*)&a_s[k][mt];
        float4 wv = *(const float4*)&w_s[k][jt];
        acc[0][0] += av.x * wv.x; acc[0][1] += av.x * wv.y; acc[0][2] += av.x * wv.z; acc[0][3] += av.x * wv.w;
        acc[1][0] += av.y * wv.x; acc[1][1] += av.y * wv.y; acc[1][2] += av.y * wv.z; acc[1][3] += av.y * wv.w;
        acc[2][0] += av.z * wv.x; acc[2][1] += av.z * wv.y; acc[2][2] += av.z * wv.z; acc[2][3] += av.z * wv.w;
        acc[3][0] += av.w * wv.x; acc[3][1] += av.w * wv.y; acc[3][2] += av.w * wv.z; acc[3][3] += av.w * wv.w;
    }

    const float* b1t = b1 + t * HH;
    float bj[4], ssj[4], csj[4];
#pragma unroll
    for (int j = 0; j < 4; j++) {
        bj[j]  = b1t[jt + j];
        ssj[j] = g_ss[jt + j];
        csj[j] = g_cs[jt + j];
    }
#pragma unroll
    for (int i = 0; i < 4; i++) {
        int n = m0 + mt + i;
        if (n < NN) {
            float o[4];
#pragma unroll
            for (int j = 0; j < 4; j++) {
                float z = acc[i][j] + bj[j];
                z = (z > 0.f) ? z : expm1f(z);
                o[j] = z * ssj[j] + csj[j];
            }
            *(float4*)&g_h2[n * HH + jt] = make_float4(o[0], o[1], o[2], o[3]);
        }
    }
}

// ---------------- step kernel 2: agg(h2) -> GEMM2 -> PLIF -> spike -> decode
// dynamic smem: a_s[96*68] | w_s[96*96] | lws[96] | nacc[64]
#define SMEM2_FLOATS (HH * 68 + HH * HH + HH + 64)
__global__ __launch_bounds__(384, 3) void k_step2(
    const float* __restrict__ w2, const float* __restrict__ b2,
    const float* __restrict__ tau, float* __restrict__ out, int t)
{
    extern __shared__ float dsm[];
    float* a_s  = dsm;                    // [96][68]
    float* w_s  = dsm + HH * 68;          // [96][96]
    float* lws  = w_s + HH * HH;          // [96]
    float* nacc = lws + HH;               // [64]

    int tid  = threadIdx.x;
    int warp = tid >> 5;
    int lane = tid & 31;
    int m0   = blockIdx.x * 64;

    if (tid < HH) lws[tid] = g_lwsum[tid];
    if (tid < 64) nacc[tid] = 0.f;
    for (int idx = tid; idx < HH * HH; idx += 384)
        w_s[idx] = w2[idx];

    // fused aggregation: lane handles channels 2*lane, 2*lane+1, 64+lane
    for (int m = warp; m < 64; m += 12) {
        int n = m0 + m;
        if (n >= NN) {
            a_s[(2 * lane) * 68 + m]     = 0.f;
            a_s[(2 * lane + 1) * 68 + m] = 0.f;
            a_s[(64 + lane) * 68 + m]    = 0.f;
            continue;
        }
        const float* hb = g_h2 + n * HH;
        float sn = g_snorm[n];
        float2 hv = __ldcg((const float2*)hb + lane);
        float a0 = sn * hv.x;
        float a1 = sn * hv.y;
        float a2 = sn * __ldcg(hb + 64 + lane);
        int e0 = g_off[n], e1 = g_off[n + 1];
#pragma unroll 4
        for (int e = e0; e < e1; e++) {
            int2  p = __ldcg(&g_epack[e]);
            float w = __int_as_float(p.y);
            const float* hs = g_h2 + p.x * HH;
            float2 v = __ldcg((const float2*)hs + lane);
            a0 += w * v.x;
            a1 += w * v.y;
            a2 += w * __ldcg(hs + 64 + lane);
        }
        a_s[(2 * lane) * 68 + m]     = a0;
        a_s[(2 * lane + 1) * 68 + m] = a1;
        a_s[(64 + lane) * 68 + m]    = a2;
    }
    __syncthreads();

    int mt = (tid & 15) * 4;
    int jt = (tid >> 4) * 4;
    float acc[4][4] = {};
#pragma unroll 8
    for (int k = 0; k < HH; k++) {
        float4 av = *(const float4*)&a_s[k * 68 + mt];
        float4 wv = *(const float4*)&w_s[k * HH + jt];
        acc[0][0] += av.x * wv.x; acc[0][1] += av.x * wv.y; acc[0][2] += av.x * wv.z; acc[0][3] += av.x * wv.w;
        acc[1][0] += av.y * wv.x; acc[1][1] += av.y * wv.y; acc[1][2] += av.y * wv.z; acc[1][3] += av.y * wv.w;
        acc[2][0] += av.z * wv.x; acc[2][1] += av.z * wv.y; acc[2][2] += av.z * wv.z; acc[2][3] += av.z * wv.w;
        acc[3][0] += av.w * wv.x; acc[3][1] += av.w * wv.y; acc[3][2] += av.w * wv.z; acc[3][3] += av.w * wv.w;
    }

    float tauv = *tau;
    float bj[4], lj[4];
#pragma unroll
    for (int j = 0; j < 4; j++) { bj[j] = b2[jt + j]; lj[j] = lws[jt + j]; }

#pragma unroll
    for (int i = 0; i < 4; i++) {
        int n = m0 + mt + i;
        if (n < NN) {
            float4 vv = *(float4*)&g_v[n * HH + jt];
            float vc[4] = {vv.x, vv.y, vv.z, vv.w};
            float vo[4];
            float pl = 0.f;
#pragma unroll
            for (int j = 0; j < 4; j++) {
                float dv = acc[i][j] + bj[j];
                float q  = dv - vc[j];
                float vnew = vc[j] + ((tauv == 1.0f) ? q : q / tauv);
                float u = vnew - VTH;
                bool sp = (u > 0.f);
                vo[j] = sp ? 0.f : vnew;
                if (sp) pl += lj[j];
            }
            *(float4*)&g_v[n * HH + jt] = make_float4(vo[0], vo[1], vo[2], vo[3]);
            atomicAdd(&nacc[mt + i], pl);
        }
    }
    __syncthreads();
    if (tid < 64) {
        int n = m0 + tid;
        if (n < NN) out[t * NN + n] = nacc[tid];
    }
}

// ---------------- launch --------------------------------------------------
extern "C" void kernel_launch(void* const* d_in, const int* in_sizes, int n_in,
                              void* d_out, int out_size) {
    const float* x      = (const float*)d_in[0];
    const int*   ei     = (const int*)  d_in[1];
    const float* w1     = (const float*)d_in[2];
    const float* b1     = (const float*)d_in[3];
    const float* bn1_g  = (const float*)d_in[4];
    const float* bn1_b  = (const float*)d_in[5];
    const float* bn1_m  = (const float*)d_in[6];
    const float* bn1_v  = (const float*)d_in[7];
    const float* bns_g  = (const float*)d_in[8];
    const float* bns_b  = (const float*)d_in[9];
    const float* bns_m  = (const float*)d_in[10];
    const float* bns_v  = (const float*)d_in[11];
    const float* w2     = (const float*)d_in[12];
    const float* b2     = (const float*)d_in[13];
    const float* lin_w  = (const float*)d_in[14];
    const float* tau    = (const float*)d_in[15];
    float* out = (float*)d_out;

    static bool attr_set = false;
    if (!attr_set) {
        cudaFuncSetAttribute(k_step2, cudaFuncAttributeMaxDynamicSharedMemorySize,
                             SMEM2_FLOATS * (int)sizeof(float));
        attr_set = true;
    }

    // exactly 5 preprocessing launches
    k_pre0<<<(NN * HH + 255) / 256, 256>>>(bns_g, bns_b, bns_m, bns_v, lin_w,
                                           bn1_g, bn1_b, bn1_m, bn1_v);
    k_deg<<<(EE + 255) / 256, 256>>>(ei);
    k_scan_dinv<<<1, 1024>>>();
    k_fill<<<(EE + 255) / 256, 256>>>(ei);
    k_rsum<<<(NN + 255) / 256, 256>>>();

    int nb_gemm = (NN + 63) / 64;        // 782
    for (int t = 0; t < TT; t++) {
        k_step1<<<nb_gemm, 384>>>(x, w1, b1, t);
        k_step2<<<nb_gemm, 384, SMEM2_FLOATS * (int)sizeof(float)>>>(w2, b2, tau, out, t);
    }
}

// round 11
// speedup vs baseline: 1.3295x; 1.2691x over previous
#include <cuda_runtime.h>
#include <math.h>

#define NN    50000
#define EE    800000
#define TT    32
#define CH    64          // CHUNK = CIN/T
#define HH    96
#define CIN   2048
#define EPS_BN 1e-5f
#define VTH    0.005f

// ---------------- persistent device scratch (no allocation allowed) -------
__device__ int   g_deg[NN];
__device__ int   g_cnt[NN];
__device__ int   g_off[NN + 1];
__device__ int2  g_epack[EE];           // {src, weight bits}
__device__ float g_dinv[NN];
__device__ float g_snorm[NN];
__device__ float g_rsum[NN];
__device__ float g_ss[HH];              // shared-BN scale
__device__ float g_cs[HH];              // shared-BN shift
__device__ float g_lwsum[HH];           // sum(lin_w, axis=0)
__device__ float g_s1[TT * CH];         // input-BN scale, all steps
__device__ float g_c1[TT * CH];         // input-BN shift, all steps
__device__ float g_h2all[(size_t)TT * NN * HH];   // bns(elu(gcn1)) for all t
__device__ float g_dvall[(size_t)TT * NN * HH];   // gcn2 output (dv) for all t

// ---------------- preprocessing (exactly 5 launches) ----------------------
// NOTE: grid must cover NN — g_deg/g_cnt MUST be reset every call, or state
// leaks across graph replays and k_fill writes out of bounds.
__global__ void k_pre0(const float* __restrict__ bg, const float* __restrict__ bb,
                       const float* __restrict__ bm, const float* __restrict__ bv,
                       const float* __restrict__ lw,
                       const float* __restrict__ g1, const float* __restrict__ b1,
                       const float* __restrict__ m1, const float* __restrict__ v1) {
    int i = blockIdx.x * blockDim.x + threadIdx.x;
    if (i < NN) { g_deg[i] = 0; g_cnt[i] = 0; }
    if (i < TT * CH) {
        float s = g1[i] * rsqrtf(v1[i] + EPS_BN);
        g_s1[i] = s;
        g_c1[i] = b1[i] - m1[i] * s;
    }
    if (i < HH) {
        float s = bg[i] * rsqrtf(bv[i] + EPS_BN);
        g_ss[i] = s;
        g_cs[i] = bb[i] - bm[i] * s;
        float acc = 0.f;
        for (int o = 0; o < HH; o++) acc += lw[o * HH + i];
        g_lwsum[i] = acc;
    }
}

__global__ void k_deg(const int* __restrict__ ei) {
    int e = blockIdx.x * blockDim.x + threadIdx.x;
    if (e < EE) atomicAdd(&g_deg[ei[EE + e]], 1);
}

__global__ void k_scan_dinv() {
    __shared__ int buf[1024];
    __shared__ int carry;
    int tid = threadIdx.x;
    if (tid == 0) carry = 0;
    __syncthreads();
    for (int base = 0; base < NN; base += 1024) {
        int i = base + tid;
        int val = 0;
        if (i < NN) {
            val = g_deg[i];
            float d = (float)(val + 1);
            g_dinv[i]  = rsqrtf(d);
            g_snorm[i] = 1.0f / d;
        }
        buf[tid] = val;
        __syncthreads();
        for (int off = 1; off < 1024; off <<= 1) {
            int t2 = (tid >= off) ? buf[tid - off] : 0;
            __syncthreads();
            buf[tid] += t2;
            __syncthreads();
        }
        if (i < NN) g_off[i] = carry + buf[tid] - val;   // exclusive
        __syncthreads();
        if (tid == 0) carry += buf[1023];
        __syncthreads();
    }
    if (tid == 0) g_off[NN] = carry;
}

__global__ void k_fill(const int* __restrict__ ei) {
    int e = blockIdx.x * blockDim.x + threadIdx.x;
    if (e < EE) {
        int s = ei[e];
        int d = ei[EE + e];
        int pos = g_off[d] + atomicAdd(&g_cnt[d], 1);
        g_epack[pos] = make_int2(s, __float_as_int(g_dinv[s] * g_dinv[d]));
    }
}

__global__ void k_rsum() {
    int n = blockIdx.x * blockDim.x + threadIdx.x;
    if (n < NN) {
        float r = g_snorm[n];
        int e1 = g_off[n + 1];
        for (int e = g_off[n]; e < e1; e++) r += __int_as_float(g_epack[e].y);
        g_rsum[n] = r;
    }
}

// ---------------- fused kernel 1 (ALL t in one launch) --------------------
// block (bx, t): agg(x chunk t)+BN fold -> GEMM1(64->96) -> elu -> bns -> h2all[t]
__global__ __launch_bounds__(384) void k_fused1(
    const float* __restrict__ x, const float* __restrict__ w1,
    const float* __restrict__ b1)
{
    __shared__ float a_s[CH][68];     // [k][m]
    __shared__ float w_s[CH][HH];

    int t    = blockIdx.y;
    int tid  = threadIdx.x;
    int warp = tid >> 5;
    int lane = tid & 31;
    int m0   = blockIdx.x * 64;

    const float* wt = w1 + t * CH * HH;
    for (int idx = tid; idx < CH * HH; idx += 384)
        w_s[idx / HH][idx % HH] = wt[idx];

    // fused aggregation: lane handles channels 2*lane, 2*lane+1 (float2)
    const float* s1 = g_s1 + t * CH;
    const float* c1 = g_c1 + t * CH;
    float s1a = s1[2 * lane], s1b = s1[2 * lane + 1];
    float c1a = c1[2 * lane], c1b = c1[2 * lane + 1];
    for (int m = warp; m < 64; m += 12) {
        int n = m0 + m;
        if (n >= NN) { a_s[2 * lane][m] = 0.f; a_s[2 * lane + 1][m] = 0.f; continue; }
        const float2* xb = (const float2*)(x + (size_t)n * CIN + t * CH);
        float sn = g_snorm[n];
        float2 xv = xb[lane];
        float a0 = sn * xv.x;
        float a1 = sn * xv.y;
        int e0 = g_off[n], e1 = g_off[n + 1];
#pragma unroll 4
        for (int e = e0; e < e1; e++) {
            int2  p = g_epack[e];
            float w = __int_as_float(p.y);
            float2 v = ((const float2*)(x + (size_t)p.x * CIN + t * CH))[lane];
            a0 += w * v.x;
            a1 += w * v.y;
        }
        float r = g_rsum[n];
        a_s[2 * lane][m]     = a0 * s1a + r * c1a;
        a_s[2 * lane + 1][m] = a1 * s1b + r * c1b;
    }
    __syncthreads();

    int mt = (tid & 15) * 4;   // 0..60
    int jt = (tid >> 4) * 4;   // 0..92
    float acc[4][4] = {};
#pragma unroll 8
    for (int k = 0; k < CH; k++) {
        float4 av = *(const float4*)&a_s[k][mt];
        float4 wv = *(const float4*)&w_s[k][jt];
        acc[0][0] += av.x * wv.x; acc[0][1] += av.x * wv.y; acc[0][2] += av.x * wv.z; acc[0][3] += av.x * wv.w;
        acc[1][0] += av.y * wv.x; acc[1][1] += av.y * wv.y; acc[1][2] += av.y * wv.z; acc[1][3] += av.y * wv.w;
        acc[2][0] += av.z * wv.x; acc[2][1] += av.z * wv.y; acc[2][2] += av.z * wv.z; acc[2][3] += av.z * wv.w;
        acc[3][0] += av.w * wv.x; acc[3][1] += av.w * wv.y; acc[3][2] += av.w * wv.z; acc[3][3] += av.w * wv.w;
    }

    const float* b1t = b1 + t * HH;
    float bj[4], ssj[4], csj[4];
#pragma unroll
    for (int j = 0; j < 4; j++) {
        bj[j]  = b1t[jt + j];
        ssj[j] = g_ss[jt + j];
        csj[j] = g_cs[jt + j];
    }
    float* h2 = g_h2all + (size_t)t * NN * HH;
#pragma unroll
    for (int i = 0; i < 4; i++) {
        int n = m0 + mt + i;
        if (n < NN) {
            float o[4];
#pragma unroll
            for (int j = 0; j < 4; j++) {
                float z = acc[i][j] + bj[j];
                z = (z > 0.f) ? z : expm1f(z);
                o[j] = z * ssj[j] + csj[j];
            }
            *(float4*)&h2[(size_t)n * HH + jt] = make_float4(o[0], o[1], o[2], o[3]);
        }
    }
}

// ---------------- fused kernel 2 (ALL t in one launch) --------------------
// block (bx, t): agg(h2all[t]) -> GEMM2(96->96)+b2 -> dvall[t]
#define SMEM2_FLOATS (HH * 68 + HH * HH)
__global__ __launch_bounds__(384) void k_fused2(
    const float* __restrict__ w2, const float* __restrict__ b2)
{
    extern __shared__ float dsm[];
    float* a_s = dsm;                    // [96][68]
    float* w_s = dsm + HH * 68;          // [96][96]

    int t    = blockIdx.y;
    int tid  = threadIdx.x;
    int warp = tid >> 5;
    int lane = tid & 31;
    int m0   = blockIdx.x * 64;

    for (int idx = tid; idx < HH * HH; idx += 384)
        w_s[idx] = w2[idx];

    const float* h2 = g_h2all + (size_t)t * NN * HH;
    for (int m = warp; m < 64; m += 12) {
        int n = m0 + m;
        if (n >= NN) {
            a_s[(2 * lane) * 68 + m]     = 0.f;
            a_s[(2 * lane + 1) * 68 + m] = 0.f;
            a_s[(64 + lane) * 68 + m]    = 0.f;
            continue;
        }
        const float* hb = h2 + (size_t)n * HH;
        float sn = g_snorm[n];
        float2 hv = ((const float2*)hb)[lane];
        float a0 = sn * hv.x;
        float a1 = sn * hv.y;
        float a2 = sn * hb[64 + lane];
        int e0 = g_off[n], e1 = g_off[n + 1];
#pragma unroll 4
        for (int e = e0; e < e1; e++) {
            int2  p = g_epack[e];
            float w = __int_as_float(p.y);
            const float* hs = h2 + (size_t)p.x * HH;
            float2 v = ((const float2*)hs)[lane];
            a0 += w * v.x;
            a1 += w * v.y;
            a2 += w * hs[64 + lane];
        }
        a_s[(2 * lane) * 68 + m]     = a0;
        a_s[(2 * lane + 1) * 68 + m] = a1;
        a_s[(64 + lane) * 68 + m]    = a2;
    }
    __syncthreads();

    int mt = (tid & 15) * 4;
    int jt = (tid >> 4) * 4;
    float acc[4][4] = {};
#pragma unroll 8
    for (int k = 0; k < HH; k++) {
        float4 av = *(const float4*)&a_s[k * 68 + mt];
        float4 wv = *(const float4*)&w_s[k * HH + jt];
        acc[0][0] += av.x * wv.x; acc[0][1] += av.x * wv.y; acc[0][2] += av.x * wv.z; acc[0][3] += av.x * wv.w;
        acc[1][0] += av.y * wv.x; acc[1][1] += av.y * wv.y; acc[1][2] += av.y * wv.z; acc[1][3] += av.y * wv.w;
        acc[2][0] += av.z * wv.x; acc[2][1] += av.z * wv.y; acc[2][2] += av.z * wv.z; acc[2][3] += av.z * wv.w;
        acc[3][0] += av.w * wv.x; acc[3][1] += av.w * wv.y; acc[3][2] += av.w * wv.z; acc[3][3] += av.w * wv.w;
    }

    float bj[4];
#pragma unroll
    for (int j = 0; j < 4; j++) bj[j] = b2[jt + j];

    float* dv = g_dvall + (size_t)t * NN * HH;
#pragma unroll
    for (int i = 0; i < 4; i++) {
        int n = m0 + mt + i;
        if (n < NN) {
            *(float4*)&dv[(size_t)n * HH + jt] =
                make_float4(acc[i][0] + bj[0], acc[i][1] + bj[1],
                            acc[i][2] + bj[2], acc[i][3] + bj[3]);
        }
    }
}

// ---------------- PLIF scan: one warp per node, loop over t ---------------
__global__ __launch_bounds__(256) void k_plif(const float* __restrict__ tau,
                                              float* __restrict__ out)
{
    int gw   = (blockIdx.x * blockDim.x + threadIdx.x) >> 5;
    int lane = threadIdx.x & 31;
    if (gw >= NN) return;

    float l0 = g_lwsum[lane];
    float l1 = g_lwsum[lane + 32];
    float l2 = g_lwsum[lane + 64];
    float tauv = *tau;
    float rtau = 1.0f / tauv;

    float v0 = 0.f, v1 = 0.f, v2 = 0.f;
    size_t base = (size_t)gw * HH;
#pragma unroll 4
    for (int t = 0; t < TT; t++) {
        const float* dvp = g_dvall + (size_t)t * NN * HH + base;
        float d0 = dvp[lane];
        float d1 = dvp[lane + 32];
        float d2 = dvp[lane + 64];
        float n0 = v0 + (d0 - v0) * rtau;
        float n1 = v1 + (d1 - v1) * rtau;
        float n2 = v2 + (d2 - v2) * rtau;
        bool s0 = (n0 - VTH) > 0.f;
        bool s1 = (n1 - VTH) > 0.f;
        bool s2 = (n2 - VTH) > 0.f;
        v0 = s0 ? 0.f : n0;
        v1 = s1 ? 0.f : n1;
        v2 = s2 ? 0.f : n2;
        float pl = (s0 ? l0 : 0.f) + (s1 ? l1 : 0.f) + (s2 ? l2 : 0.f);
#pragma unroll
        for (int off = 16; off > 0; off >>= 1)
            pl += __shfl_down_sync(0xffffffff, pl, off);
        if (lane == 0) out[t * NN + gw] = pl;
    }
}

// ---------------- launch --------------------------------------------------
extern "C" void kernel_launch(void* const* d_in, const int* in_sizes, int n_in,
                              void* d_out, int out_size) {
    const float* x      = (const float*)d_in[0];
    const int*   ei     = (const int*)  d_in[1];
    const float* w1     = (const float*)d_in[2];
    const float* b1     = (const float*)d_in[3];
    const float* bn1_g  = (const float*)d_in[4];
    const float* bn1_b  = (const float*)d_in[5];
    const float* bn1_m  = (const float*)d_in[6];
    const float* bn1_v  = (const float*)d_in[7];
    const float* bns_g  = (const float*)d_in[8];
    const float* bns_b  = (const float*)d_in[9];
    const float* bns_m  = (const float*)d_in[10];
    const float* bns_v  = (const float*)d_in[11];
    const float* w2     = (const float*)d_in[12];
    const float* b2     = (const float*)d_in[13];
    const float* lin_w  = (const float*)d_in[14];
    const float* tau    = (const float*)d_in[15];
    float* out = (float*)d_out;

    static bool attr_set = false;
    if (!attr_set) {
        cudaFuncSetAttribute(k_fused2, cudaFuncAttributeMaxDynamicSharedMemorySize,
                             SMEM2_FLOATS * (int)sizeof(float));
        attr_set = true;
    }

    // exactly 5 preprocessing launches (grid covers NN for state reset!)
    k_pre0<<<(NN + 255) / 256, 256>>>(bns_g, bns_b, bns_m, bns_v, lin_w,
                                      bn1_g, bn1_b, bn1_m, bn1_v);
    k_deg<<<(EE + 255) / 256, 256>>>(ei);
    k_scan_dinv<<<1, 1024>>>();
    k_fill<<<(EE + 255) / 256, 256>>>(ei);
    k_rsum<<<(NN + 255) / 256, 256>>>();

    // 3 dense hot-loop launches
    int nb = (NN + 63) / 64;             // 782 node tiles
    dim3 grid(nb, TT);
    k_fused1<<<grid, 384>>>(x, w1, b1);
    k_fused2<<<grid, 384, SMEM2_FLOATS * (int)sizeof(float)>>>(w2, b2);
    k_plif<<<(NN * 32 + 255) / 256, 256>>>(tau, out);
}